// round 9
// baseline (speedup 1.0000x reference)
#include <cuda_runtime.h>
#include <cuda_fp16.h>
#include <cstdint>

// ---------------------------------------------------------------------------
// Problem constants
// ---------------------------------------------------------------------------
#define M_TOTAL 4096            // 4 * 1024
#define N_TOTAL 11008
#define K_TOTAL 4096
#define PACKED_LEN (N_TOTAL * K_TOTAL / 4)   // int32 elements, one byte each

#define BM 128
#define BN 128
#define BK 64                   // k-elems per stage (A: 128B row; B: 64 e4m3 B)
#define S_STAGES (K_TOTAL / BK) // 64
#define NTHREADS 128
#define NSTAGES 4

#define M_TILES (M_TOTAL / BM)          // 32
#define N_TILES (N_TOTAL / BN)          // 86
#define NTILES  (M_TILES * N_TILES)     // 2752
#define GRID    296                     // persistent: 2 CTAs per SM

// SMEM per stage: A fp16 tile 16KB + B e4m3 tile 128 rows x 80B pitch
#define A_TILE_BYTES 16384
#define B_ROW_PITCH  80         // 64B data + 16B pad -> conflict-free LDS.32
#define B_TILE_BYTES (128 * B_ROW_PITCH)                   // 10240
#define STAGE_BYTES  (A_TILE_BYTES + B_TILE_BYTES)         // 26624
#define SMEM_TOTAL_BYTES (NSTAGES * STAGE_BYTES)           // 106496

// Prep kernel grid split
#define CONV_BLOCKS ((M_TOTAL * K_TOTAL / 4) / 256)    // 16384
#define DEQ_BLOCKS  ((PACKED_LEN / 4) / 256)           // 11008
#define PREP_BLOCKS (CONV_BLOCKS + DEQ_BLOCKS)

// ---------------------------------------------------------------------------
// Device scratch (module-static; no runtime allocation)
// ---------------------------------------------------------------------------
__device__ __half  g_A[(size_t)M_TOTAL * K_TOTAL];      // 32 MB, x in fp16
__device__ uint8_t g_Bp[(size_t)N_TOTAL * K_TOTAL];     // 44 MB, W as e4m3 (permuted)

// ---------------------------------------------------------------------------
// PTX helpers (baseline ISA: cp.async sm_80, ldmatrix sm_75, mma sm_80,
// cvt f16x2<-e4m3x2 sm_89)
// ---------------------------------------------------------------------------
static __device__ __forceinline__ uint32_t smem_u32(const void* p) {
    uint32_t a;
    asm("{ .reg .u64 t; cvta.to.shared.u64 t, %1; cvt.u32.u64 %0, t; }"
        : "=r"(a) : "l"(p));
    return a;
}

#define CP_ASYNC16(dst, src) \
    asm volatile("cp.async.cg.shared.global [%0], [%1], 16;" \
                 :: "r"(dst), "l"(src) : "memory")
#define CP_COMMIT() asm volatile("cp.async.commit_group;" ::: "memory")
#define CP_WAIT1()  asm volatile("cp.async.wait_group 1;" ::: "memory")

#define LDMATRIX_X4(r0, r1, r2, r3, addr) \
    asm volatile("ldmatrix.sync.aligned.m8n8.x4.shared.b16 {%0,%1,%2,%3}, [%4];" \
                 : "=r"(r0), "=r"(r1), "=r"(r2), "=r"(r3) : "r"(addr))

// Load one 32-bit word of permuted e4m3 B and convert to two f16x2 frag regs.
#define B_DEQUANT(f0, f1, addr) do { \
    uint32_t _w; \
    asm volatile("ld.shared.b32 %0, [%1];" : "=r"(_w) : "r"(addr)); \
    asm volatile("{ .reg .b16 lo, hi; mov.b32 {lo, hi}, %2;\n\t" \
                 "cvt.rn.f16x2.e4m3x2 %0, lo;\n\t" \
                 "cvt.rn.f16x2.e4m3x2 %1, hi; }" \
                 : "=r"(f0), "=r"(f1) : "r"(_w)); \
} while (0)

// D = A*B + D, m16n8k16, f16 in, f32 acc
#define MMA_16816(c0, c1, c2, c3, a0, a1, a2, a3, b0, b1) \
    asm volatile("mma.sync.aligned.m16n8k16.row.col.f32.f16.f16.f32 " \
                 "{%0,%1,%2,%3}, {%4,%5,%6,%7}, {%8,%9}, {%0,%1,%2,%3};" \
                 : "+f"(c0), "+f"(c1), "+f"(c2), "+f"(c3) \
                 : "r"(a0), "r"(a1), "r"(a2), "r"(a3), "r"(b0), "r"(b1))

// SW128 swizzle of a byte offset within a [row][128B] tile (A only)
#define SW128(off) ((off) ^ (((off) >> 3) & 0x70))

// ---------------------------------------------------------------------------
// Fused prologue: x f32->fp16 AND weight repack to permuted e4m3.
// e4m3 for {-1,0,1,2}: 0xB8, 0x00, 0x38, 0x40 (exact).
// Per 16-k group, byte order permuted so GEMM lane q's LDS.32 at offset q*4
// yields halves (k=2q,2q+1, 2q+8,2q+9): pair p goes to byte (p%4)*4+(p/4)*2.
// ---------------------------------------------------------------------------
#define E4M3_LUT 0x403800B8u

static __device__ __forceinline__ uint32_t pairA(unsigned b) {   // fields 0,1
    unsigned sel = (b & 3u) | ((b & 0xCu) << 2);
    return __byte_perm(E4M3_LUT, 0u, sel);
}
static __device__ __forceinline__ uint32_t pairB(unsigned b) {   // fields 2,3
    unsigned sel = ((b >> 4) & 3u) | ((b & 0xC0u) >> 2);
    return __byte_perm(E4M3_LUT, 0u, sel);
}

__global__ void __launch_bounds__(256) prep_kernel(
    const float4* __restrict__ x, const int4* __restrict__ pw)
{
    int b = blockIdx.x;
    if (b < CONV_BLOCKS) {
        int i = b * 256 + threadIdx.x;
        float4 v = x[i];
        __half2* A2 = reinterpret_cast<__half2*>(g_A);
        A2[2 * i]     = __floats2half2_rn(v.x, v.y);
        A2[2 * i + 1] = __floats2half2_rn(v.z, v.w);
    } else {
        int i = (b - CONV_BLOCKS) * 256 + threadIdx.x;   // one 16-k group
        int4 p = pw[i];
        unsigned b0 = (unsigned)p.x & 0xFF, b1 = (unsigned)p.y & 0xFF;
        unsigned b2 = (unsigned)p.z & 0xFF, b3 = (unsigned)p.w & 0xFF;
        // pairs: byte j holds pairs 2j (fields0,1), 2j+1 (fields2,3)
        uint32_t pA0 = pairA(b0), pB0 = pairB(b0);
        uint32_t pA1 = pairA(b1), pB1 = pairB(b1);
        uint32_t pA2 = pairA(b2), pB2 = pairB(b2);
        uint32_t pA3 = pairA(b3), pB3 = pairB(b3);
        uint4 o;
        o.x = __byte_perm(pA0, pA2, 0x5410);   // bytes 0-3:  pair0 | pair4
        o.y = __byte_perm(pB0, pB2, 0x5410);   // bytes 4-7:  pair1 | pair5
        o.z = __byte_perm(pA1, pA3, 0x5410);   // bytes 8-11: pair2 | pair6
        o.w = __byte_perm(pB1, pB3, 0x5410);   // bytes12-15: pair3 | pair7
        reinterpret_cast<uint4*>(g_Bp)[i] = o;
    }
}

// ---------------------------------------------------------------------------
// Stage loader (no commit; caller commits). 128 threads:
// A: 1024 16B chunks -> 8/thread (SW128 rows). B: thread t = row t, 4 chunks
// of 16B into its 80B-pitch smem row.
// ---------------------------------------------------------------------------
static __device__ __forceinline__ void load_stage(
    int buf, int st, uint32_t smem_base, uint32_t swBase, int tid,
    const char* gA, const char* gB)
{
    uint32_t aB = smem_base + (uint32_t)buf * STAGE_BYTES + swBase;
    const char* As = gA + (size_t)st * (BK * 2);
    #pragma unroll
    for (int c = 0; c < 8; c++)
        CP_ASYNC16(aB + 2048u * c, As + (size_t)c * 16 * K_TOTAL * 2);

    uint32_t bB = smem_base + (uint32_t)buf * STAGE_BYTES + A_TILE_BYTES
                + (uint32_t)tid * B_ROW_PITCH;
    const char* Bs = gB + (size_t)st * BK;     // 64 bytes per row per stage
    #pragma unroll
    for (int c = 0; c < 4; c++)
        CP_ASYNC16(bB + 16u * c, Bs + 16u * c);
}

// ---------------------------------------------------------------------------
// Persistent GEMM, 2 CTAs/SM: 128x128 CTA tile, 4 warps (2Mx2N), warp tile
// 64x64. 4-stage pipeline, WAIT1 at loop top guarantees stage s AND s+1
// resident (race-free cross-stage fragment prefetch). B fragments built by
// LDS.32 + e4m3->f16x2 cvt (no B LDSM) -> smem crossbar off critical path.
// ---------------------------------------------------------------------------
__global__ void __launch_bounds__(NTHREADS, 2)
gemm_kernel(const float* __restrict__ scale_p, float* __restrict__ out)
{
    extern __shared__ char smem[];
    uint32_t smem_base = smem_u32(smem);
    int tid = threadIdx.x;
    int wid = tid >> 5;
    int lid = tid & 31;

    int warp_m = (wid & 1) * 64;   // 0 or 64
    int warp_n = (wid >> 1) * 64;  // 0 or 64

    // ---- cp.async per-thread constants (A) ----
    int ldRow = tid >> 3;          // 0..15
    int ldCol = tid & 7;
    uint32_t swBase = SW128((uint32_t)(ldRow * 128 + ldCol * 16));

    // ---- A ldmatrix constants ----
    int mat  = lid >> 3;
    int r    = lid & 7;
    int rowA0 = warp_m + ((mat & 1) << 3) + r;
    uint32_t cxor = (uint32_t)(((mat >> 1) << 4)) ^ ((uint32_t)r << 4);
    uint32_t arA[4];
    #pragma unroll
    for (int mi = 0; mi < 4; mi++) arA[mi] = (uint32_t)((rowA0 + mi * 16) * 128);

    // ---- B LDS per-lane base: row = warp_n + lid/4 (+ni offsets), word lid%4
    uint32_t laneB = (uint32_t)(warp_n + (lid >> 2)) * B_ROW_PITCH
                   + (uint32_t)(lid & 3) * 4 + A_TILE_BYTES;
    // per-ni immediates: (ni>>1)*16 rows, (ni&1)*8 rows
    // -> offset = (ni>>1)*1280 + (ni&1)*640 ; per-ks: +16

    float scale = *scale_p;

    // ---- load cursor (runs continuously across tiles) ----
    int ldTile  = blockIdx.x;
    int ldStage = 0;
    const char* gAl = reinterpret_cast<const char*>(
        g_A + (size_t)((ldTile & 31) * BM + ldRow) * K_TOTAL + ldCol * 8);
    const char* gBl = reinterpret_cast<const char*>(
        g_Bp + (size_t)((ldTile >> 5) * BN + tid) * K_TOTAL);

    // Prime 3 stages (buffers 0,1,2)
    #pragma unroll
    for (int p = 0; p < 3; p++) {
        load_stage(ldStage & 3, ldStage, smem_base, swBase, tid, gAl, gBl);
        CP_COMMIT();
        ldStage++;
    }
    CP_WAIT1();                  // stages 0,1 resident
    __syncthreads();

    uint32_t a_frag[2][4][4];
    uint32_t b_frag[2][8][2];

    // Preload first tile, stage 0, ks 0 fragments into frag buffer 0
    {
        #pragma unroll
        for (int mi = 0; mi < 4; mi++)
            LDMATRIX_X4(a_frag[0][mi][0], a_frag[0][mi][1],
                        a_frag[0][mi][2], a_frag[0][mi][3],
                        smem_base + arA[mi] + cxor);
        uint32_t bT = smem_base + laneB;
        #pragma unroll
        for (int ni = 0; ni < 8; ni++)
            B_DEQUANT(b_frag[0][ni][0], b_frag[0][ni][1],
                      bT + (uint32_t)((ni >> 1) * 1280 + (ni & 1) * 640));
    }

    float acc[4][8][4];
    #pragma unroll
    for (int mi = 0; mi < 4; mi++)
        #pragma unroll
        for (int ni = 0; ni < 8; ni++)
            #pragma unroll
            for (int c = 0; c < 4; c++) acc[mi][ni][c] = 0.0f;

    for (int tile = blockIdx.x; tile < NTILES; tile += GRID) {
        int mBase = (tile & 31) * BM;
        int nBase = (tile >> 5) * BN;
        bool last_tile = (tile + GRID >= NTILES);

        for (int s = 0; s < S_STAGES; s++) {
            // All but newest group complete -> stages s AND s+1 resident.
            CP_WAIT1();
            __syncthreads();

            // Issue stage s+3; empty commit at tail keeps group math uniform.
            if (ldTile < NTILES)
                load_stage(ldStage & 3, ldStage, smem_base, swBase, tid, gAl, gBl);
            CP_COMMIT();
            if (++ldStage == S_STAGES) {
                ldStage = 0;
                ldTile += GRID;
                if (ldTile < NTILES) {
                    gAl = reinterpret_cast<const char*>(
                        g_A + (size_t)((ldTile & 31) * BM + ldRow) * K_TOTAL + ldCol * 8);
                    gBl = reinterpret_cast<const char*>(
                        g_Bp + (size_t)((ldTile >> 5) * BN + tid) * K_TOTAL);
                }
            }

            uint32_t stageT = smem_base + (uint32_t)(s & 3) * STAGE_BYTES;
            uint32_t nextT  = smem_base + (uint32_t)((s + 1) & 3) * STAGE_BYTES;

            #pragma unroll
            for (int ks = 0; ks < 4; ks++) {
                int cur = ks & 1;
                int nxt = cur ^ 1;

                // Prefetch: ks+1 of this stage, or ks=0 of the next stage
                // (possibly the next tile's stage 0 — same buffer rotation).
                uint32_t pT, pkb, pbo;
                bool do_pref;
                if (ks < 3) {
                    pT = stageT;
                    pkb = (uint32_t)((ks + 1) * 32) ^ cxor;
                    pbo = (uint32_t)((ks + 1) * 16);
                    do_pref = true;
                } else {
                    pT = nextT;
                    pkb = cxor;
                    pbo = 0;
                    do_pref = (s + 1 < S_STAGES) || !last_tile;
                }
                uint32_t pB = pT + laneB + pbo;

                // 8 groups of 4 MMAs; interleave 4 A-LDSM + 8 B-dequants
                #pragma unroll
                for (int g = 0; g < 8; g++) {
                    if (do_pref) {
                        if (g < 4)
                            LDMATRIX_X4(a_frag[nxt][g][0], a_frag[nxt][g][1],
                                        a_frag[nxt][g][2], a_frag[nxt][g][3],
                                        pT + arA[g] + pkb);
                        B_DEQUANT(b_frag[nxt][g][0], b_frag[nxt][g][1],
                                  pB + (uint32_t)((g >> 1) * 1280 + (g & 1) * 640));
                    }
                    int mi = g & 3;
                    int nh = (g >> 2) * 4;
                    #pragma unroll
                    for (int nj = 0; nj < 4; nj++) {
                        int ni = nh + nj;
                        MMA_16816(acc[mi][ni][0], acc[mi][ni][1],
                                  acc[mi][ni][2], acc[mi][ni][3],
                                  a_frag[cur][mi][0], a_frag[cur][mi][1],
                                  a_frag[cur][mi][2], a_frag[cur][mi][3],
                                  b_frag[cur][ni][0], b_frag[cur][ni][1]);
                    }
                }
            }
        }

        // Epilogue (next tile's loads already in flight; co-resident CTA
        // keeps the tensor pipe busy meanwhile).
        int erow = lid >> 2;
        int ecol = (lid & 3) * 2;
        #pragma unroll
        for (int mi = 0; mi < 4; mi++) {
            #pragma unroll
            for (int ni = 0; ni < 8; ni++) {
                int row = mBase + warp_m + mi * 16 + erow;
                int col = nBase + warp_n + ni * 8 + ecol;
                float2 v0 = make_float2(acc[mi][ni][0] * scale, acc[mi][ni][1] * scale);
                float2 v1 = make_float2(acc[mi][ni][2] * scale, acc[mi][ni][3] * scale);
                *reinterpret_cast<float2*>(out + (size_t)row * N_TOTAL + col) = v0;
                *reinterpret_cast<float2*>(out + (size_t)(row + 8) * N_TOTAL + col) = v1;
                acc[mi][ni][0] = 0.0f; acc[mi][ni][1] = 0.0f;
                acc[mi][ni][2] = 0.0f; acc[mi][ni][3] = 0.0f;
            }
        }
    }
}

// ---------------------------------------------------------------------------
// Harness entry
// ---------------------------------------------------------------------------
extern "C" void kernel_launch(void* const* d_in, const int* in_sizes, int n_in,
                              void* d_out, int out_size)
{
    const float* x  = (const float*)d_in[0];
    const int*   pw = (const int*)d_in[1];
    const float* ws = (const float*)d_in[2];
    float* out = (float*)d_out;

    cudaFuncSetAttribute(gemm_kernel,
                         cudaFuncAttributeMaxDynamicSharedMemorySize,
                         SMEM_TOTAL_BYTES);

    prep_kernel<<<PREP_BLOCKS, 256>>>(
        reinterpret_cast<const float4*>(x),
        reinterpret_cast<const int4*>(pw));
    gemm_kernel<<<GRID, NTHREADS, SMEM_TOTAL_BYTES>>>(ws, out);
}